// round 7
// baseline (speedup 1.0000x reference)
#include <cuda_runtime.h>

// out[b,f] = x[b,f] * (log_sigma[f] < 1.0f ? e : 1.0f)
// BATCH=65536, N_FEATURES=4096 -> 2^26 float4. Pure HBM stream (2.15 GB).
//
// R7: converged form. Fine-grained launch (1 float4 per thread, 262144
// blocks) — empirically the best wall-clock geometry (perfect CLC
// work-leveling, zero tail quantum) — plus streaming cache hints
// (evict-first for the zero-reuse x/out streams; keeps the 16KB
// log_sigma table cache-resident).
//
// Measured across 6 structural variants: DRAM pinned at 83-86% / ~6.8TB/s
// regardless of SM-side structure. This is the r/w-stream HBM ceiling.

#define N_FEATURES   4096
#define VEC4_PER_ROW (N_FEATURES / 4)            // 1024, power of two
#define TOTAL_VEC4   (65536LL * VEC4_PER_ROW)    // 2^26

#define THREADS 256

__global__ void __launch_bounds__(THREADS)
svdropout2d_kernel(const float4* __restrict__ x,
                   const float4* __restrict__ log_sigma,
                   float4* __restrict__ out)
{
    const float E = 2.71828182845904523536f;

    long long i = (long long)blockIdx.x * THREADS + threadIdx.x;

    // column (in float4 units) within the row — power-of-two mask, no div
    int c = (int)(i & (VEC4_PER_ROW - 1));

    float4 ls = __ldg(&log_sigma[c]);   // 16 KB, cache-resident
    float4 v  = __ldcs(&x[i]);          // streaming read, evict-first

    v.x *= (ls.x < 1.0f) ? E : 1.0f;
    v.y *= (ls.y < 1.0f) ? E : 1.0f;
    v.z *= (ls.z < 1.0f) ? E : 1.0f;
    v.w *= (ls.w < 1.0f) ? E : 1.0f;

    __stcs(&out[i], v);                 // streaming write, evict-first
}

extern "C" void kernel_launch(void* const* d_in, const int* in_sizes, int n_in,
                              void* d_out, int out_size)
{
    const float4* x  = (const float4*)d_in[0];
    const float4* ls = (const float4*)d_in[1];
    float4* out      = (float4*)d_out;

    const unsigned blocks = (unsigned)(TOTAL_VEC4 / THREADS);  // 262144, exact

    svdropout2d_kernel<<<blocks, THREADS>>>(x, ls, out);
}

// round 8
// speedup vs baseline: 1.0190x; 1.0190x over previous
#include <cuda_runtime.h>

// out[b,f] = x[b,f] * (log_sigma[f] < 1.0f ? e : 1.0f)
// BATCH=65536, N_FEATURES=4096 -> 2^26 float4. Pure HBM stream (2.15 GB).
//
// R8: fine-grained, 2 float4 per thread (131072 blocks x 256 thr).
// Halves per-element launch/index/issue overhead vs the 1-float4 form
// while keeping near-perfect CLC wave leveling and MLP=2 per thread.
// Plain ld/st: cache hints measured as non-levers (R7 vs R1).
//
// The second element is +NSTRIDE float4s away (NSTRIDE = total threads,
// a multiple of 1024), so the per-row column index — and hence the scale
// vector — is shared by both elements: one log_sigma load per thread.

#define N_FEATURES   4096
#define VEC4_PER_ROW (N_FEATURES / 4)            // 1024, power of two
#define TOTAL_VEC4   (65536LL * VEC4_PER_ROW)    // 2^26

#define THREADS  256
#define BLOCKS   131072                           // 2^25 threads
#define NSTRIDE  ((long long)THREADS * BLOCKS)    // 2^25, multiple of 1024

__global__ void __launch_bounds__(THREADS)
svdropout2d_kernel(const float4* __restrict__ x,
                   const float4* __restrict__ log_sigma,
                   float4* __restrict__ out)
{
    const float E = 2.71828182845904523536f;

    const long long i = (long long)blockIdx.x * THREADS + threadIdx.x;

    // Same column for both elements (stride % 1024 == 0): one scale load.
    const int c = (int)(i & (VEC4_PER_ROW - 1));
    const float4 ls = __ldg(&log_sigma[c]);

    float4 s;
    s.x = (ls.x < 1.0f) ? E : 1.0f;
    s.y = (ls.y < 1.0f) ? E : 1.0f;
    s.z = (ls.z < 1.0f) ? E : 1.0f;
    s.w = (ls.w < 1.0f) ? E : 1.0f;

    float4 v0 = x[i];
    float4 v1 = x[i + NSTRIDE];

    v0.x *= s.x; v0.y *= s.y; v0.z *= s.z; v0.w *= s.w;
    v1.x *= s.x; v1.y *= s.y; v1.z *= s.z; v1.w *= s.w;

    out[i]           = v0;
    out[i + NSTRIDE] = v1;
}

extern "C" void kernel_launch(void* const* d_in, const int* in_sizes, int n_in,
                              void* d_out, int out_size)
{
    const float4* x  = (const float4*)d_in[0];
    const float4* ls = (const float4*)d_in[1];
    float4* out      = (float4*)d_out;

    svdropout2d_kernel<<<BLOCKS, THREADS>>>(x, ls, out);
}